// round 2
// baseline (speedup 1.0000x reference)
#include <cuda_runtime.h>
#include <cuda_bf16.h>
#include <math.h>

// ---------------- static scratch (no runtime allocation allowed) ----------------
#define MAXN 50000
#define MAXE 800000
#define NEG_SLOPE 0.2f

__device__ __align__(16) float g_h1[MAXN * 128];    // layer1 linear output
__device__ __align__(16) float g_out1[MAXN * 128];  // layer1 GAT output
__device__ __align__(16) float g_h2[MAXN * 40];     // layer2 linear output
__device__ __align__(16) float g_as1[MAXN * 8];
__device__ __align__(16) float g_ad1[MAXN * 8];
__device__ __align__(16) float g_as2[MAXN];
__device__ __align__(16) float g_ad2[MAXN];
__device__ int g_deg[MAXN + 1];
__device__ int g_offs[MAXN + 1];
__device__ int g_cur[MAXN];
__device__ int g_srcs[MAXE + MAXN];   // CSR column (src) indices, grouped by dst

// ---------------- CSR construction ----------------
__global__ void init_deg_kernel(int N) {
    int i = blockIdx.x * blockDim.x + threadIdx.x;
    if (i < N) g_deg[i] = 1;   // self loop
}

__global__ void hist_kernel(const int* __restrict__ ei, int E, int N) {
    int e = blockIdx.x * blockDim.x + threadIdx.x;
    if (e < E) {
        int d = ei[E + e];
        if (d >= 0 && d < N) atomicAdd(&g_deg[d], 1);
    }
}

// single-block exclusive scan over g_deg -> g_offs, g_cur
__global__ void scan_kernel(int N) {
    __shared__ int sums[1024];
    int t = threadIdx.x;
    int chunk = (N + 1023) / 1024;
    int lo = t * chunk;
    int hi = lo + chunk; if (hi > N) hi = N;
    if (lo > N) lo = N;
    int s = 0;
    for (int i = lo; i < hi; i++) s += g_deg[i];
    sums[t] = s;
    __syncthreads();
    for (int off = 1; off < 1024; off <<= 1) {
        int v = 0;
        if (t >= off) v = sums[t - off];
        __syncthreads();
        sums[t] += v;
        __syncthreads();
    }
    int run = (t > 0) ? sums[t - 1] : 0;
    for (int i = lo; i < hi; i++) {
        g_offs[i] = run;
        g_cur[i] = run;
        run += g_deg[i];
    }
    if (t == 1023) g_offs[N] = sums[1023];
}

__global__ void scatter_kernel(const int* __restrict__ ei, int E, int N) {
    int e = blockIdx.x * blockDim.x + threadIdx.x;
    if (e < E) {
        int d = ei[E + e];
        int s = ei[e];
        if (d >= 0 && d < N && s >= 0 && s < N) {
            int p = atomicAdd(&g_cur[d], 1);
            if (p < MAXE + MAXN) g_srcs[p] = s;
        }
    }
}

__global__ void selfloop_kernel(int N) {
    int i = blockIdx.x * blockDim.x + threadIdx.x;
    if (i < N) {
        int p = atomicAdd(&g_cur[i], 1);
        if (p < MAXE + MAXN) g_srcs[p] = i;
    }
}

// ---------------- layer-1 GEMM: h1 = x @ W1   (Nx128 @ 128x128) ----------------
// block tile 64(M) x 128(N), K staged by 16. 256 threads, thread tile 8x4.
__global__ void gemm1_kernel(const float* __restrict__ X, const float* __restrict__ W, int N) {
    __shared__ float Xs[64][16];
    __shared__ float Ws[16][128];
    int tid = threadIdx.x;
    int tcol = tid & 31;   // 32 col-groups of 4
    int trow = tid >> 5;   // 8 row-groups of 8
    int block_m = blockIdx.x * 64;

    float acc[8][4];
#pragma unroll
    for (int m = 0; m < 8; m++)
#pragma unroll
        for (int j = 0; j < 4; j++) acc[m][j] = 0.f;

    for (int kk = 0; kk < 128; kk += 16) {
        // load Xs (64x16): one float4 per thread
        {
            int r = tid >> 2;
            int c = (tid & 3) * 4;
            int gm = block_m + r;
            float4 v = make_float4(0.f, 0.f, 0.f, 0.f);
            if (gm < N) v = *(const float4*)&X[gm * 128 + kk + c];
            *(float4*)&Xs[r][c] = v;
        }
        // load Ws (16x128): two float4 per thread
        {
            int r = tid >> 5;
            int c = (tid & 31) * 4;
            *(float4*)&Ws[r][c]     = *(const float4*)&W[(kk + r) * 128 + c];
            *(float4*)&Ws[r + 8][c] = *(const float4*)&W[(kk + r + 8) * 128 + c];
        }
        __syncthreads();
#pragma unroll
        for (int k = 0; k < 16; k++) {
            float b[4];
#pragma unroll
            for (int j = 0; j < 4; j++) b[j] = Ws[k][tcol * 4 + j];
#pragma unroll
            for (int m = 0; m < 8; m++) {
                float a = Xs[trow * 8 + m][k];
#pragma unroll
                for (int j = 0; j < 4; j++) acc[m][j] = fmaf(a, b[j], acc[m][j]);
            }
        }
        __syncthreads();
    }
#pragma unroll
    for (int m = 0; m < 8; m++) {
        int gm = block_m + trow * 8 + m;
        if (gm < N) {
            float4 o = make_float4(acc[m][0], acc[m][1], acc[m][2], acc[m][3]);
            *(float4*)&g_h1[gm * 128 + tcol * 4] = o;
        }
    }
}

// ---------------- layer-1 attention scalars ----------------
__global__ void attn1_kernel(const float* __restrict__ att_s, const float* __restrict__ att_d, int N) {
    int idx = blockIdx.x * blockDim.x + threadIdx.x;  // one per (n, head)
    int n = idx >> 3, h = idx & 7;
    if (n >= N) return;
    const float* hp = &g_h1[n * 128 + h * 16];
    float s = 0.f, d = 0.f;
#pragma unroll
    for (int c = 0; c < 16; c += 4) {
        float4 v = *(const float4*)&hp[c];
        float4 a = *(const float4*)&att_s[h * 16 + c];
        float4 b = *(const float4*)&att_d[h * 16 + c];
        s += v.x * a.x + v.y * a.y + v.z * a.z + v.w * a.w;
        d += v.x * b.x + v.y * b.y + v.z * b.z + v.w * b.w;
    }
    g_as1[idx] = s;
    g_ad1[idx] = d;
}

__device__ __forceinline__ float lrelu(float a) { return a > 0.f ? a : NEG_SLOPE * a; }

// ---------------- layer-1 aggregation: one warp per dst node ----------------
__global__ void agg1_kernel(const float* __restrict__ bias, int N) {
    int gw = (blockIdx.x * blockDim.x + threadIdx.x) >> 5;
    int lane = threadIdx.x & 31;
    int nwarps = (gridDim.x * blockDim.x) >> 5;
    for (int i = gw; i < N; i += nwarps) {
        int start = g_offs[i], end = g_offs[i + 1];
        float ad[8];
        {
            float4 d0 = *(const float4*)&g_ad1[i * 8];
            float4 d1 = *(const float4*)&g_ad1[i * 8 + 4];
            ad[0] = d0.x; ad[1] = d0.y; ad[2] = d0.z; ad[3] = d0.w;
            ad[4] = d1.x; ad[5] = d1.y; ad[6] = d1.z; ad[7] = d1.w;
        }
        float m[8];
#pragma unroll
        for (int h = 0; h < 8; h++) m[h] = -1e30f;
        // pass A: segment max, lane-parallel over edges
        for (int e = start + lane; e < end; e += 32) {
            int s = g_srcs[e];
            float4 s0 = *(const float4*)&g_as1[s * 8];
            float4 s1 = *(const float4*)&g_as1[s * 8 + 4];
            float av[8] = {s0.x, s0.y, s0.z, s0.w, s1.x, s1.y, s1.z, s1.w};
#pragma unroll
            for (int h = 0; h < 8; h++) {
                float a = lrelu(av[h] + ad[h]);
                m[h] = fmaxf(m[h], a);
            }
        }
#pragma unroll
        for (int off = 16; off; off >>= 1)
#pragma unroll
            for (int h = 0; h < 8; h++)
                m[h] = fmaxf(m[h], __shfl_xor_sync(0xffffffffu, m[h], off));

        int c0 = lane * 4;
        int hh = lane >> 2;
        float mh = m[0], adh = ad[0];
#pragma unroll
        for (int q = 1; q < 8; q++) {
            if (hh == q) { mh = m[q]; adh = ad[q]; }
        }
        // pass B: serial over edges, lanes own 4 channels each
        float acc0 = 0.f, acc1 = 0.f, acc2 = 0.f, acc3 = 0.f, denom = 0.f;
        for (int e = start; e < end; e++) {
            int s = g_srcs[e];
            float a = lrelu(g_as1[s * 8 + hh] + adh);
            float ee = __expf(a - mh);
            denom += ee;
            float4 hv = *(const float4*)&g_h1[s * 128 + c0];
            acc0 = fmaf(ee, hv.x, acc0);
            acc1 = fmaf(ee, hv.y, acc1);
            acc2 = fmaf(ee, hv.z, acc2);
            acc3 = fmaf(ee, hv.w, acc3);
        }
        float inv = 1.0f / (denom + 1e-16f);
        float4 o;
        o.x = acc0 * inv + bias[c0];
        o.y = acc1 * inv + bias[c0 + 1];
        o.z = acc2 * inv + bias[c0 + 2];
        o.w = acc3 * inv + bias[c0 + 3];
        *(float4*)&g_out1[i * 128 + c0] = o;
    }
}

// ---------------- layer-2 GEMM + attention scalars ----------------
// h2 = out1 @ W2 (Nx128 @ 128x40), fused a_src2/a_dst2. One warp -> 4 nodes.
__global__ void gemm2_kernel(const float* __restrict__ W, const float* __restrict__ att_s,
                             const float* __restrict__ att_d, int N) {
    __shared__ float Ws[128 * 40];
    __shared__ float Xsw[8][4][128];
    int tid = threadIdx.x;
    for (int i = tid; i < 128 * 40; i += 256) Ws[i] = W[i];
    int w = tid >> 5, lane = tid & 31;
    int n0 = (blockIdx.x * 8 + w) * 4;
    __syncthreads();
    if (n0 >= N) return;  // warp-uniform; no further __syncthreads below

#pragma unroll
    for (int r = 0; r < 4; r++) {
        int n = n0 + r;
        float4 v = make_float4(0.f, 0.f, 0.f, 0.f);
        if (n < N) v = *(const float4*)&g_out1[n * 128 + lane * 4];
        *(float4*)&Xsw[w][r][lane * 4] = v;
    }
    __syncwarp();

    float acc[4][2];
#pragma unroll
    for (int r = 0; r < 4; r++) { acc[r][0] = 0.f; acc[r][1] = 0.f; }

    for (int k = 0; k < 128; k++) {
        float w0 = Ws[k * 40 + lane];
        float w1 = (lane < 8) ? Ws[k * 40 + 32 + lane] : 0.f;
#pragma unroll
        for (int r = 0; r < 4; r++) {
            float xv = Xsw[w][r][k];
            acc[r][0] = fmaf(xv, w0, acc[r][0]);
            acc[r][1] = fmaf(xv, w1, acc[r][1]);
        }
    }

    float asl = att_s[lane];
    float ash = (lane < 8) ? att_s[32 + lane] : 0.f;
    float adl = att_d[lane];
    float adh = (lane < 8) ? att_d[32 + lane] : 0.f;
#pragma unroll
    for (int r = 0; r < 4; r++) {
        int n = n0 + r;
        if (n >= N) break;
        g_h2[n * 40 + lane] = acc[r][0];
        if (lane < 8) g_h2[n * 40 + 32 + lane] = acc[r][1];
        float sa = acc[r][0] * asl + acc[r][1] * ash;
        float da = acc[r][0] * adl + acc[r][1] * adh;
#pragma unroll
        for (int off = 16; off; off >>= 1) {
            sa += __shfl_xor_sync(0xffffffffu, sa, off);
            da += __shfl_xor_sync(0xffffffffu, da, off);
        }
        if (lane == 0) { g_as2[n] = sa; g_ad2[n] = da; }
    }
}

// ---------------- layer-2 aggregation: one warp per dst node ----------------
__global__ void agg2_kernel(const float* __restrict__ bias, float* __restrict__ out, int N) {
    int gw = (blockIdx.x * blockDim.x + threadIdx.x) >> 5;
    int lane = threadIdx.x & 31;
    int nwarps = (gridDim.x * blockDim.x) >> 5;
    for (int i = gw; i < N; i += nwarps) {
        int start = g_offs[i], end = g_offs[i + 1];
        float adh = g_ad2[i];
        float mm = -1e30f;
        for (int e = start + lane; e < end; e += 32) {
            int s = g_srcs[e];
            mm = fmaxf(mm, lrelu(g_as2[s] + adh));
        }
#pragma unroll
        for (int off = 16; off; off >>= 1)
            mm = fmaxf(mm, __shfl_xor_sync(0xffffffffu, mm, off));

        float acc0 = 0.f, acc1 = 0.f, denom = 0.f;
        for (int e = start; e < end; e++) {
            int s = g_srcs[e];
            float a = lrelu(g_as2[s] + adh);
            float ee = __expf(a - mm);
            denom += ee;
            acc0 = fmaf(ee, g_h2[s * 40 + lane], acc0);
            if (lane < 8) acc1 = fmaf(ee, g_h2[s * 40 + 32 + lane], acc1);
        }
        float inv = 1.0f / (denom + 1e-16f);
        out[i * 40 + lane] = acc0 * inv + bias[lane];
        if (lane < 8) out[i * 40 + 32 + lane] = acc1 * inv + bias[32 + lane];
    }
}

// ---------------- launch ----------------
extern "C" void kernel_launch(void* const* d_in, const int* in_sizes, int n_in,
                              void* d_out, int out_size) {
    const float* x   = (const float*)d_in[0];
    const int*   ei  = (const int*)d_in[1];   // jax downcasts int64 -> int32 (x64 disabled)
    const float* W1  = (const float*)d_in[2];
    const float* as1 = (const float*)d_in[3];
    const float* ad1 = (const float*)d_in[4];
    const float* b1  = (const float*)d_in[5];
    const float* W2  = (const float*)d_in[6];
    const float* as2 = (const float*)d_in[7];
    const float* ad2 = (const float*)d_in[8];
    const float* b2  = (const float*)d_in[9];
    float* out = (float*)d_out;

    int N = in_sizes[0] / 128;
    int E = in_sizes[1] / 2;
    if (N > MAXN) N = MAXN;
    if (E > MAXE) E = MAXE;

    // CSR build (shared by both layers)
    init_deg_kernel<<<(N + 255) / 256, 256>>>(N);
    hist_kernel<<<(E + 255) / 256, 256>>>(ei, E, N);
    scan_kernel<<<1, 1024>>>(N);
    scatter_kernel<<<(E + 255) / 256, 256>>>(ei, E, N);
    selfloop_kernel<<<(N + 255) / 256, 256>>>(N);

    // layer 1
    gemm1_kernel<<<(N + 63) / 64, 256>>>(x, W1, N);
    attn1_kernel<<<(N * 8 + 255) / 256, 256>>>(as1, ad1, N);
    agg1_kernel<<<(N + 7) / 8, 256>>>(b1, N);

    // layer 2
    gemm2_kernel<<<(((N + 3) / 4) + 7) / 8, 256>>>(W2, as2, ad2, N);
    agg2_kernel<<<(N + 7) / 8, 256>>>(b2, out, N);
}